// round 3
// baseline (speedup 1.0000x reference)
#include <cuda_runtime.h>

#define D_MODEL 1024
#define N_HEADS 16
#define HEAD    64
#define BATCH   2
#define SEQ     2048
#define M_TOT   (BATCH * SEQ)

__device__ float g_qp[M_TOT * D_MODEL];
__device__ float g_kp[M_TOT * D_MODEL];
__device__ float g_vp[M_TOT * D_MODEL];

// ---------------------------------------------------------------------------
__device__ __forceinline__ unsigned f2tf(float x) {
    unsigned r;
    asm("cvt.rna.tf32.f32 %0, %1;" : "=r"(r) : "f"(x));
    return r;
}

__device__ __forceinline__ void mma8(float* d, const unsigned* a, const unsigned* b) {
    asm volatile(
        "mma.sync.aligned.m16n8k8.row.col.f32.tf32.tf32.f32 "
        "{%0,%1,%2,%3}, {%4,%5,%6,%7}, {%8,%9}, {%0,%1,%2,%3};\n"
        : "+f"(d[0]), "+f"(d[1]), "+f"(d[2]), "+f"(d[3])
        : "r"(a[0]), "r"(a[1]), "r"(a[2]), "r"(a[3]), "r"(b[0]), "r"(b[1]));
}

// e^x with FMA/ALU only (valid x<=0, clamped at -80)
__device__ __forceinline__ float fast_exp(float x) {
    x = fmaxf(x, -80.0f);
    float y  = x * 1.44269504088896f;
    float fy = y + 12582912.0f;
    int   k  = __float_as_int(fy);
    float f  = y - (fy - 12582912.0f);
    float p  = 1.33336e-3f;
    p = fmaf(p, f, 9.61812e-3f);
    p = fmaf(p, f, 5.55041e-2f);
    p = fmaf(p, f, 2.40226507e-1f);
    p = fmaf(p, f, 6.93147182e-1f);
    p = fmaf(p, f, 1.0f);
    return __int_as_float(__float_as_int(p) + (k << 23));
}

// ---------------------------------------------------------------------------
// Projection GEMM, fragment-major smem. Block 128x128, BK=16, 8 warps (2Mx4N),
// warp tile 64x32 (4 m16 x 4 n8). Consumer feeds mma via LDS.128 only.
// ---------------------------------------------------------------------------
__global__ __launch_bounds__(256) void proj_tc2(
    const float* __restrict__ q, const float* __restrict__ k, const float* __restrict__ v,
    const float* __restrict__ Wq, const float* __restrict__ Wk, const float* __restrict__ Wv,
    const float* __restrict__ bq, const float* __restrict__ bk, const float* __restrict__ bv,
    float* __restrict__ yq, float* __restrict__ yk, float* __restrict__ yv)
{
    const int z = blockIdx.z;
    const float* X    = (z == 0) ? q  : (z == 1) ? k  : v;
    const float* W    = (z == 0) ? Wq : (z == 1) ? Wk : Wv;
    const float* bias = (z == 0) ? bq : (z == 1) ? bk : bv;
    float*       Y    = (z == 0) ? yq : (z == 1) ? yk : yv;

    // AF: 16 groups (mb 0..7 x kk 0..1) x 32 lanes x uint4 = 2048 words
    // BF: 16 groups (nj 0..15)          x 32 lanes x uint4 = 2048 words
    __shared__ unsigned SM[4096];
    unsigned* AFw = SM;
    unsigned* BFw = SM + 2048;
    uint4* AF4 = (uint4*)AFw;
    uint4* BF4 = (uint4*)BFw;

    const int tid  = threadIdx.x;
    const int lane = tid & 31, wid = tid >> 5;
    const int wm   = wid >> 2, wn = wid & 3;
    const int g    = lane >> 2, t = lane & 3;
    const int bm   = blockIdx.y * 128, bn = blockIdx.x * 128;

    const int lr = tid >> 2;            // loader row 0..63
    const int lc = (tid & 3) * 4;       // loader col 0,4,8,12
    const float* Ap = X + (size_t)(bm + lr) * D_MODEL + lc;
    const float* Bp = W + (size_t)(bn + lr) * D_MODEL + lc;

    // precomputed scatter bases (element j adds j*4 words)
    const int a_mb = lr >> 4, a_rr = lr & 15;
    const int a_g = a_rr & 7, a_hi = a_rr >> 3;
    const int a_kk = lc >> 3, a_q4 = (lc >> 2) & 1;
    const int a_base0 = ((a_mb * 2 + a_kk) * 32 + a_g * 4) * 4 + a_hi + 2 * a_q4;
    const int a_base1 = (((a_mb + 4) * 2 + a_kk) * 32 + a_g * 4) * 4 + a_hi + 2 * a_q4; // row +64
    const int b_nj = lr >> 3, b_g = lr & 7;
    const int b_word = a_kk * 2 + a_q4;
    const int b_base0 = (b_nj * 32 + b_g * 4) * 4 + b_word;
    const int b_base1 = ((b_nj + 8) * 32 + b_g * 4) * 4 + b_word;

    float acc[4][4][4];
#pragma unroll
    for (int mi = 0; mi < 4; mi++)
#pragma unroll
        for (int nj = 0; nj < 4; nj++)
#pragma unroll
            for (int r = 0; r < 4; r++) acc[mi][nj][r] = 0.0f;

    float4 ra0 = *(const float4*)(Ap);
    float4 ra1 = *(const float4*)(Ap + (size_t)64 * D_MODEL);
    float4 rb0 = *(const float4*)(Bp);
    float4 rb1 = *(const float4*)(Bp + (size_t)64 * D_MODEL);

    for (int k0 = 0; k0 < D_MODEL; k0 += 16) {
        AFw[a_base0 + 0]  = f2tf(ra0.x); AFw[a_base0 + 4]  = f2tf(ra0.y);
        AFw[a_base0 + 8]  = f2tf(ra0.z); AFw[a_base0 + 12] = f2tf(ra0.w);
        AFw[a_base1 + 0]  = f2tf(ra1.x); AFw[a_base1 + 4]  = f2tf(ra1.y);
        AFw[a_base1 + 8]  = f2tf(ra1.z); AFw[a_base1 + 12] = f2tf(ra1.w);
        BFw[b_base0 + 0]  = f2tf(rb0.x); BFw[b_base0 + 4]  = f2tf(rb0.y);
        BFw[b_base0 + 8]  = f2tf(rb0.z); BFw[b_base0 + 12] = f2tf(rb0.w);
        BFw[b_base1 + 0]  = f2tf(rb1.x); BFw[b_base1 + 4]  = f2tf(rb1.y);
        BFw[b_base1 + 8]  = f2tf(rb1.z); BFw[b_base1 + 12] = f2tf(rb1.w);
        __syncthreads();

        if (k0 + 16 < D_MODEL) {
            ra0 = *(const float4*)(Ap + k0 + 16);
            ra1 = *(const float4*)(Ap + (size_t)64 * D_MODEL + k0 + 16);
            rb0 = *(const float4*)(Bp + k0 + 16);
            rb1 = *(const float4*)(Bp + (size_t)64 * D_MODEL + k0 + 16);
        }

#pragma unroll
        for (int kk = 0; kk < 2; kk++) {
            uint4 af[4];
#pragma unroll
            for (int mi = 0; mi < 4; mi++)
                af[mi] = AF4[((wm * 4 + mi) * 2 + kk) * 32 + lane];
#pragma unroll
            for (int nj = 0; nj < 4; nj++) {
                uint4 bf = BF4[(wn * 4 + nj) * 32 + lane];
                const unsigned* bh = kk ? &bf.z : &bf.x;
#pragma unroll
                for (int mi = 0; mi < 4; mi++)
                    mma8(acc[mi][nj], &af[mi].x, bh);
            }
        }
        __syncthreads();
    }

#pragma unroll
    for (int mi = 0; mi < 4; mi++) {
        int r0 = bm + wm * 64 + mi * 16 + g;
#pragma unroll
        for (int nj = 0; nj < 4; nj++) {
            int c = bn + wn * 32 + nj * 8 + 2 * t;
            float b0v = bias[c], b1v = bias[c + 1];
            *(float2*)(Y + (size_t)r0 * D_MODEL + c) =
                make_float2(acc[mi][nj][0] + b0v, acc[mi][nj][1] + b1v);
            *(float2*)(Y + (size_t)(r0 + 8) * D_MODEL + c) =
                make_float2(acc[mi][nj][2] + b0v, acc[mi][nj][3] + b1v);
        }
    }
}

// ---------------------------------------------------------------------------
// Flash attention. 128 thr / 4 warps, 64 q-rows (16/warp), key tiles of 64.
// K/V in fragment-major smem (LDS.128 consumer). Q frags hoisted to regs.
// P relayout C-frag->A-frag via shfl (no smem round-trip).
// ---------------------------------------------------------------------------
__device__ __forceinline__ void p_relayout(const float* s, unsigned* a, int lane, int t) {
    const int srcA = (lane & 28) | (t >> 1);
    const int srcB = srcA + 2;
    float u0 = __shfl_sync(0xffffffffu, s[0], srcA);
    float u1 = __shfl_sync(0xffffffffu, s[1], srcA);
    float v0 = __shfl_sync(0xffffffffu, s[2], srcA);
    float v1 = __shfl_sync(0xffffffffu, s[3], srcA);
    float w0 = __shfl_sync(0xffffffffu, s[0], srcB);
    float w1 = __shfl_sync(0xffffffffu, s[1], srcB);
    float x0 = __shfl_sync(0xffffffffu, s[2], srcB);
    float x1 = __shfl_sync(0xffffffffu, s[3], srcB);
    bool odd = (t & 1);
    a[0] = f2tf(odd ? u1 : u0);
    a[1] = f2tf(odd ? v1 : v0);
    a[2] = f2tf(odd ? w1 : w0);
    a[3] = f2tf(odd ? x1 : x0);
}

__global__ __launch_bounds__(128) void attn_tc2(
    const float* __restrict__ QP, const float* __restrict__ KP,
    const float* __restrict__ VP, const float* __restrict__ mask,
    float* __restrict__ out)
{
    __shared__ uint4 KF[1024];   // 16 KB: (nj*4+kp)*32 + lane
    __shared__ uint4 VF[1024];   // 16 KB
    unsigned* KFw = (unsigned*)KF;
    unsigned* VFw = (unsigned*)VF;

    const int tid  = threadIdx.x;
    const int lane = tid & 31, wid = tid >> 5;
    const int g    = lane >> 2, t = lane & 3;
    const int rw   = wid * 16;
    const int q0   = blockIdx.x * 64;
    const int h    = blockIdx.y;
    const int b    = blockIdx.z;
    const size_t base = (size_t)b * SEQ * D_MODEL + (size_t)h * HEAD;

    const int r0g = q0 + rw + g;
    const int r1g = r0g + 8;

    // Hoist Q fragments (pre-scaled by 1/8)
    unsigned qa[8][4];
    {
        const float* Q0 = QP + base + (size_t)r0g * D_MODEL;
        const float* Q1 = QP + base + (size_t)r1g * D_MODEL;
#pragma unroll
        for (int kc = 0; kc < 8; kc++) {
            qa[kc][0] = f2tf(Q0[kc * 8 + t]     * 0.125f);
            qa[kc][1] = f2tf(Q1[kc * 8 + t]     * 0.125f);
            qa[kc][2] = f2tf(Q0[kc * 8 + t + 4] * 0.125f);
            qa[kc][3] = f2tf(Q1[kc * 8 + t + 4] * 0.125f);
        }
    }

    float o[8][4];
#pragma unroll
    for (int nj = 0; nj < 8; nj++)
#pragma unroll
        for (int r = 0; r < 4; r++) o[nj][r] = 0.0f;
    float m0 = -1e30f, m1 = -1e30f, l0 = 0.0f, l1 = 0.0f;

    const float* mp0 = mask + (size_t)r0g * SEQ;
    const float* mp1 = mask + (size_t)r1g * SEQ;

    // loader constants (tile-invariant): 8 chunks of (row, c4)
    const int lr_b = tid >> 4;           // chunk p adds 8
    const int lc4  = tid & 15;
    // K scatter base for this thread (element j adds j*4)
    const int k_kp   = lc4 >> 2;
    const int k_word = ((lc4 >> 1) & 1) * 2 + (lc4 & 1);
    // V scatter pieces
    const int v_nj  = lc4 >> 1;
    const int v_g0  = (lc4 & 1) * 4;

    for (int k0 = 0; k0 < SEQ; k0 += 64) {
        __syncthreads();
#pragma unroll
        for (int p = 0; p < 8; p++) {
            const int r = lr_b + p * 8;
            const float* Kp = KP + base + (size_t)(k0 + r) * D_MODEL + lc4 * 4;
            const float* Vp = VP + base + (size_t)(k0 + r) * D_MODEL + lc4 * 4;
            float4 kv = *(const float4*)Kp;
            float4 vv = *(const float4*)Vp;
            // K: row r -> nj=r>>3, g=r&7 ; cols from lc4
            {
                const int nj = r >> 3, gk = r & 7;
                unsigned* dst = KFw + ((nj * 4 + k_kp) * 32 + gk * 4) * 4 + k_word;
                dst[0]  = f2tf(kv.x); dst[4]  = f2tf(kv.y);
                dst[8]  = f2tf(kv.z); dst[12] = f2tf(kv.w);
            }
            // V: row r is key dim -> kp=r>>4, word from r ; lane from cols
            {
                const int kp = r >> 4;
                const int word = ((r >> 3) & 1) * 2 + ((r >> 2) & 1);
                const int rt = r & 3;
                unsigned* dst = VFw + ((v_nj * 4 + kp) * 32 + v_g0 * 4 + rt) * 4 + word;
                dst[0]  = f2tf(vv.x); dst[16] = f2tf(vv.y);
                dst[32] = f2tf(vv.z); dst[48] = f2tf(vv.w);
            }
        }
        __syncthreads();

        // S = Q @ K^T
        float s[8][4];
#pragma unroll
        for (int nj = 0; nj < 8; nj++)
#pragma unroll
            for (int r = 0; r < 4; r++) s[nj][r] = 0.0f;
#pragma unroll
        for (int kp = 0; kp < 4; kp++)
#pragma unroll
            for (int nj = 0; nj < 8; nj++) {
                uint4 kf = KF[(nj * 4 + kp) * 32 + lane];
                mma8(s[nj], qa[2 * kp],     &kf.x);
                mma8(s[nj], qa[2 * kp + 1], &kf.z);
            }

        // mask + row max
        float mx0 = -1e30f, mx1 = -1e30f;
#pragma unroll
        for (int nj = 0; nj < 8; nj++) {
            float2 mk0 = *(const float2*)(mp0 + k0 + nj * 8 + 2 * t);
            float2 mk1 = *(const float2*)(mp1 + k0 + nj * 8 + 2 * t);
            s[nj][0] += mk0.x; s[nj][1] += mk0.y;
            s[nj][2] += mk1.x; s[nj][3] += mk1.y;
            mx0 = fmaxf(mx0, fmaxf(s[nj][0], s[nj][1]));
            mx1 = fmaxf(mx1, fmaxf(s[nj][2], s[nj][3]));
        }
        mx0 = fmaxf(mx0, __shfl_xor_sync(0xffffffffu, mx0, 1));
        mx0 = fmaxf(mx0, __shfl_xor_sync(0xffffffffu, mx0, 2));
        mx1 = fmaxf(mx1, __shfl_xor_sync(0xffffffffu, mx1, 1));
        mx1 = fmaxf(mx1, __shfl_xor_sync(0xffffffffu, mx1, 2));

        float mn0 = fmaxf(m0, mx0), mn1 = fmaxf(m1, mx1);
        float c0 = fast_exp(m0 - mn0), c1 = fast_exp(m1 - mn1);
        float sum0 = 0.0f, sum1 = 0.0f;
#pragma unroll
        for (int nj = 0; nj < 8; nj++) {
            s[nj][0] = fast_exp(s[nj][0] - mn0);
            s[nj][1] = fast_exp(s[nj][1] - mn0);
            s[nj][2] = fast_exp(s[nj][2] - mn1);
            s[nj][3] = fast_exp(s[nj][3] - mn1);
            sum0 += s[nj][0] + s[nj][1];
            sum1 += s[nj][2] + s[nj][3];
        }
        sum0 += __shfl_xor_sync(0xffffffffu, sum0, 1);
        sum0 += __shfl_xor_sync(0xffffffffu, sum0, 2);
        sum1 += __shfl_xor_sync(0xffffffffu, sum1, 1);
        sum1 += __shfl_xor_sync(0xffffffffu, sum1, 2);

        l0 = l0 * c0 + sum0;  l1 = l1 * c1 + sum1;
        m0 = mn0;             m1 = mn1;
#pragma unroll
        for (int nj = 0; nj < 8; nj++) {
            o[nj][0] *= c0; o[nj][1] *= c0;
            o[nj][2] *= c1; o[nj][3] *= c1;
        }

        // O += P @ V  (P relayout via shfl, V from fragment-major smem)
#pragma unroll
        for (int kp = 0; kp < 4; kp++) {
            unsigned pae[4], pao[4];
            p_relayout(s[2 * kp],     pae, lane, t);
            p_relayout(s[2 * kp + 1], pao, lane, t);
#pragma unroll
            for (int oj = 0; oj < 8; oj++) {
                uint4 vf = VF[(oj * 4 + kp) * 32 + lane];
                mma8(o[oj], pae, &vf.x);
                mma8(o[oj], pao, &vf.z);
            }
        }
    }

    float inv0 = 1.0f / l0, inv1 = 1.0f / l1;
#pragma unroll
    for (int nj = 0; nj < 8; nj++) {
        *(float2*)(out + base + (size_t)r0g * D_MODEL + nj * 8 + 2 * t) =
            make_float2(o[nj][0] * inv0, o[nj][1] * inv0);
        *(float2*)(out + base + (size_t)r1g * D_MODEL + nj * 8 + 2 * t) =
            make_float2(o[nj][2] * inv1, o[nj][3] * inv1);
    }
}

// ---------------------------------------------------------------------------

extern "C" void kernel_launch(void* const* d_in, const int* in_sizes, int n_in,
                              void* d_out, int out_size)
{
    const float* q    = (const float*)d_in[0];
    const float* k    = (const float*)d_in[1];
    const float* v    = (const float*)d_in[2];
    const float* mask = (const float*)d_in[3];
    const float* Wq   = (const float*)d_in[4];
    const float* bq   = (const float*)d_in[5];
    const float* Wk   = (const float*)d_in[6];
    const float* bk   = (const float*)d_in[7];
    const float* Wv   = (const float*)d_in[8];
    const float* bv   = (const float*)d_in[9];
    float* out = (float*)d_out;

    float *qp, *kp, *vp;
    cudaGetSymbolAddress((void**)&qp, g_qp);
    cudaGetSymbolAddress((void**)&kp, g_kp);
    cudaGetSymbolAddress((void**)&vp, g_vp);

    dim3 pgrid(D_MODEL / 128, M_TOT / 128, 3);   // (8, 32, 3)
    proj_tc2<<<pgrid, 256>>>(q, k, v, Wq, Wk, Wv, bq, bk, bv, qp, kp, vp);

    attn_tc2<<<dim3(SEQ / 64, N_HEADS, BATCH), 128>>>(qp, kp, vp, mask, out);
}

// round 4
// speedup vs baseline: 1.6782x; 1.6782x over previous
#include <cuda_runtime.h>

#define D_MODEL 1024
#define N_HEADS 16
#define HEAD    64
#define BATCH   2
#define SEQ     2048
#define M_TOT   (BATCH * SEQ)

// Scratch (harness rules: __device__ globals only)
__device__ float g_qp[M_TOT * D_MODEL];
__device__ float g_kp[M_TOT * D_MODEL];
__device__ float g_vp[M_TOT * D_MODEL];
__device__ float g_xc[3][M_TOT * D_MODEL];     // tf32-converted q,k,v inputs
__device__ float g_wc[3][D_MODEL * D_MODEL];   // tf32-converted Wq,Wk,Wv

// ---------------------------------------------------------------------------
__device__ __forceinline__ unsigned f2tf(float x) {
    unsigned r;
    asm("cvt.rna.tf32.f32 %0, %1;" : "=r"(r) : "f"(x));
    return r;
}

__device__ __forceinline__ void mma8(float* d, const unsigned* a, const unsigned* b) {
    asm volatile(
        "mma.sync.aligned.m16n8k8.row.col.f32.tf32.tf32.f32 "
        "{%0,%1,%2,%3}, {%4,%5,%6,%7}, {%8,%9}, {%0,%1,%2,%3};\n"
        : "+f"(d[0]), "+f"(d[1]), "+f"(d[2]), "+f"(d[3])
        : "r"(a[0]), "r"(a[1]), "r"(a[2]), "r"(a[3]), "r"(b[0]), "r"(b[1]));
}

__device__ __forceinline__ void cp16(unsigned* smem_dst, const void* gsrc) {
    unsigned d = (unsigned)__cvta_generic_to_shared(smem_dst);
    asm volatile("cp.async.cg.shared.global [%0], [%1], 16;\n" :: "r"(d), "l"(gsrc));
}
#define CP_COMMIT asm volatile("cp.async.commit_group;\n" ::: "memory")
#define CP_WAIT0  asm volatile("cp.async.wait_group 0;\n" ::: "memory")

// e^x, FMA/ALU only (x<=0, clamped at -80)
__device__ __forceinline__ float fast_exp(float x) {
    x = fmaxf(x, -80.0f);
    float y  = x * 1.44269504088896f;
    float fy = y + 12582912.0f;
    int   k  = __float_as_int(fy);
    float f  = y - (fy - 12582912.0f);
    float p  = 1.33336e-3f;
    p = fmaf(p, f, 9.61812e-3f);
    p = fmaf(p, f, 5.55041e-2f);
    p = fmaf(p, f, 2.40226507e-1f);
    p = fmaf(p, f, 6.93147182e-1f);
    p = fmaf(p, f, 1.0f);
    return __int_as_float(__float_as_int(p) + (k << 23));
}

// ---------------------------------------------------------------------------
// Pre-convert fp32 -> tf32 bit pattern (once per tensor)
// ---------------------------------------------------------------------------
__global__ __launch_bounds__(256) void conv_tf32(
    const float4* __restrict__ s, float4* __restrict__ d, int n4)
{
    int i = blockIdx.x * 256 + threadIdx.x;
    if (i < n4) {
        float4 x = s[i];
        d[i] = make_float4(__uint_as_float(f2tf(x.x)), __uint_as_float(f2tf(x.y)),
                           __uint_as_float(f2tf(x.z)), __uint_as_float(f2tf(x.w)));
    }
}

// ---------------------------------------------------------------------------
// Projection GEMM on pre-converted tf32 data. Y = X @ W^T + b, output as tf32
// bits (Q prescaled by 0.125). Block 128x128, BK=32 double-buffered cp.async,
// 8 warps (2m x 4n), warp tile 64x32. Row stride 36 words (conflict-free).
// ---------------------------------------------------------------------------
__global__ __launch_bounds__(256) void proj_tc3(
    const float* __restrict__ x0, const float* __restrict__ x1, const float* __restrict__ x2,
    const float* __restrict__ w0, const float* __restrict__ w1, const float* __restrict__ w2,
    const float* __restrict__ bq, const float* __restrict__ bk, const float* __restrict__ bv,
    float* __restrict__ y0, float* __restrict__ y1, float* __restrict__ y2)
{
    const int z = blockIdx.z;
    const float* X    = (z == 0) ? x0 : (z == 1) ? x1 : x2;
    const float* W    = (z == 0) ? w0 : (z == 1) ? w1 : w2;
    const float* bias = (z == 0) ? bq : (z == 1) ? bk : bv;
    float*       Y    = (z == 0) ? y0 : (z == 1) ? y1 : y2;
    const float oscale = (z == 0) ? 0.125f : 1.0f;

    extern __shared__ unsigned psm[];
    unsigned* As = psm;             // [2][128*36]
    unsigned* Bs = psm + 2 * 4608;  // [2][128*36]

    const int tid = threadIdx.x, lane = tid & 31, wid = tid >> 5;
    const int wm = wid >> 2, wn = wid & 3;
    const int g = lane >> 2, t = lane & 3;
    const int bm = blockIdx.y * 128, bn = blockIdx.x * 128;

    const int frow = tid >> 3;        // 0..31, +p*32
    const int fc4  = (tid & 7) * 4;   // 0..28

    float acc[4][4][4];
#pragma unroll
    for (int mi = 0; mi < 4; mi++)
#pragma unroll
        for (int nj = 0; nj < 4; nj++)
#pragma unroll
            for (int r = 0; r < 4; r++) acc[mi][nj][r] = 0.0f;

    // prologue fill buf 0
    {
        const float* Xs = X + (size_t)bm * D_MODEL + fc4;
        const float* Ws = W + (size_t)bn * D_MODEL + fc4;
#pragma unroll
        for (int p = 0; p < 4; p++) {
            int row = frow + p * 32;
            cp16(As + row * 36 + fc4, Xs + (size_t)row * D_MODEL);
            cp16(Bs + row * 36 + fc4, Ws + (size_t)row * D_MODEL);
        }
        CP_COMMIT;
    }

    for (int it = 0; it < 32; it++) {
        CP_WAIT0;
        __syncthreads();
        if (it < 31) {
            int buf = (it + 1) & 1;
            int k0 = (it + 1) * 32;
            const float* Xs = X + (size_t)bm * D_MODEL + k0 + fc4;
            const float* Ws = W + (size_t)bn * D_MODEL + k0 + fc4;
            unsigned* Ab = As + buf * 4608;
            unsigned* Bb = Bs + buf * 4608;
#pragma unroll
            for (int p = 0; p < 4; p++) {
                int row = frow + p * 32;
                cp16(Ab + row * 36 + fc4, Xs + (size_t)row * D_MODEL);
                cp16(Bb + row * 36 + fc4, Ws + (size_t)row * D_MODEL);
            }
            CP_COMMIT;
        }
        const unsigned* Ab = As + (it & 1) * 4608;
        const unsigned* Bb = Bs + (it & 1) * 4608;
#pragma unroll
        for (int kk = 0; kk < 4; kk++) {
            unsigned af[4][4], bf[4][2];
#pragma unroll
            for (int mi = 0; mi < 4; mi++) {
                int ba = (wm * 64 + mi * 16 + g) * 36 + kk * 8 + t;
                af[mi][0] = Ab[ba];     af[mi][1] = Ab[ba + 8 * 36];
                af[mi][2] = Ab[ba + 4]; af[mi][3] = Ab[ba + 8 * 36 + 4];
            }
#pragma unroll
            for (int nj = 0; nj < 4; nj++) {
                int bb = (wn * 32 + nj * 8 + g) * 36 + kk * 8 + t;
                bf[nj][0] = Bb[bb]; bf[nj][1] = Bb[bb + 4];
            }
#pragma unroll
            for (int mi = 0; mi < 4; mi++)
#pragma unroll
                for (int nj = 0; nj < 4; nj++)
                    mma8(acc[mi][nj], af[mi], bf[nj]);
        }
    }

#pragma unroll
    for (int mi = 0; mi < 4; mi++) {
        int r0 = bm + wm * 64 + mi * 16 + g;
#pragma unroll
        for (int nj = 0; nj < 4; nj++) {
            int c = bn + wn * 32 + nj * 8 + 2 * t;
            float bb0 = bias[c], bb1 = bias[c + 1];
            float v0 = (acc[mi][nj][0] + bb0) * oscale;
            float v1 = (acc[mi][nj][1] + bb1) * oscale;
            float v2 = (acc[mi][nj][2] + bb0) * oscale;
            float v3 = (acc[mi][nj][3] + bb1) * oscale;
            *(float2*)(Y + (size_t)r0 * D_MODEL + c) =
                make_float2(__uint_as_float(f2tf(v0)), __uint_as_float(f2tf(v1)));
            *(float2*)(Y + (size_t)(r0 + 8) * D_MODEL + c) =
                make_float2(__uint_as_float(f2tf(v2)), __uint_as_float(f2tf(v3)));
        }
    }
}

// ---------------------------------------------------------------------------
// Flash attention. Inputs already tf32 bits (Q prescaled). 128 thr / 4 warps,
// q-tile 128 (32 rows/warp = 2 m16), key tiles of 64, double-buffered cp.async.
// Strides: Q/K 68 (bank = 4g+t), V 72 (bank = 8t+g) -> all conflict-free.
// ---------------------------------------------------------------------------
__device__ __forceinline__ void p_relayout(const float* s, unsigned* a, int lane, int t) {
    const int srcA = (lane & 28) | (t >> 1);
    const int srcB = srcA + 2;
    float u0 = __shfl_sync(0xffffffffu, s[0], srcA);
    float u1 = __shfl_sync(0xffffffffu, s[1], srcA);
    float v0 = __shfl_sync(0xffffffffu, s[2], srcA);
    float v1 = __shfl_sync(0xffffffffu, s[3], srcA);
    float w0 = __shfl_sync(0xffffffffu, s[0], srcB);
    float w1 = __shfl_sync(0xffffffffu, s[1], srcB);
    float x0 = __shfl_sync(0xffffffffu, s[2], srcB);
    float x1 = __shfl_sync(0xffffffffu, s[3], srcB);
    bool odd = (t & 1);
    a[0] = f2tf(odd ? u1 : u0);
    a[1] = f2tf(odd ? v1 : v0);
    a[2] = f2tf(odd ? w1 : w0);
    a[3] = f2tf(odd ? x1 : x0);
}

__global__ __launch_bounds__(128) void attn_tc3(
    const float* __restrict__ QP, const float* __restrict__ KP,
    const float* __restrict__ VP, const float* __restrict__ mask,
    float* __restrict__ out)
{
    extern __shared__ unsigned smbuf[];
    unsigned* Qs = smbuf;             // 128*68 = 8704 words
    unsigned* Ks = smbuf + 8704;      // 2 x 64*68 (4352 each)
    unsigned* Vs = smbuf + 17408;     // 2 x 64*72 (4608 each)

    const int tid = threadIdx.x, lane = tid & 31, wid = tid >> 5;
    const int g = lane >> 2, t = lane & 3;
    const int rw = wid * 32;
    const int q0 = blockIdx.x * 128;
    const int h = blockIdx.y, b = blockIdx.z;
    const size_t base = (size_t)b * SEQ * D_MODEL + (size_t)h * HEAD;

    const int frow = tid >> 4;        // 0..7
    const int fc4  = (tid & 15) * 4;  // 0..60

    // Q fill (once) + KV tile 0, one cp.async group
    {
        const float* Qsrc = QP + base + (size_t)q0 * D_MODEL + fc4;
#pragma unroll
        for (int p = 0; p < 16; p++) {
            int row = frow + p * 8;
            cp16(Qs + row * 68 + fc4, Qsrc + (size_t)row * D_MODEL);
        }
        const float* Ksrc = KP + base + fc4;
        const float* Vsrc = VP + base + fc4;
#pragma unroll
        for (int p = 0; p < 8; p++) {
            int row = frow + p * 8;
            cp16(Ks + row * 68 + fc4, Ksrc + (size_t)row * D_MODEL);
            cp16(Vs + row * 72 + fc4, Vsrc + (size_t)row * D_MODEL);
        }
        CP_COMMIT;
    }

    float o[2][8][4];
#pragma unroll
    for (int mi = 0; mi < 2; mi++)
#pragma unroll
        for (int nj = 0; nj < 8; nj++)
#pragma unroll
            for (int r = 0; r < 4; r++) o[mi][nj][r] = 0.0f;
    float mrow[4] = {-1e30f, -1e30f, -1e30f, -1e30f};
    float lrow[4] = {0.0f, 0.0f, 0.0f, 0.0f};

    for (int it = 0; it < SEQ / 64; it++) {
        CP_WAIT0;
        __syncthreads();
        if (it + 1 < SEQ / 64) {
            int buf = (it + 1) & 1;
            const float* Ksrc = KP + base + (size_t)(it + 1) * 64 * D_MODEL + fc4;
            const float* Vsrc = VP + base + (size_t)(it + 1) * 64 * D_MODEL + fc4;
            unsigned* Kb = Ks + buf * 4352;
            unsigned* Vb = Vs + buf * 4608;
#pragma unroll
            for (int p = 0; p < 8; p++) {
                int row = frow + p * 8;
                cp16(Kb + row * 68 + fc4, Ksrc + (size_t)row * D_MODEL);
                cp16(Vb + row * 72 + fc4, Vsrc + (size_t)row * D_MODEL);
            }
            CP_COMMIT;
        }
        const unsigned* Kc = Ks + (it & 1) * 4352;
        const unsigned* Vc = Vs + (it & 1) * 4608;
        const int k0 = it * 64;

        // ---- S = Q @ K^T (warp: 32 q-rows x 64 keys) ----
        float s[2][8][4];
#pragma unroll
        for (int mi = 0; mi < 2; mi++)
#pragma unroll
            for (int nj = 0; nj < 8; nj++)
#pragma unroll
                for (int r = 0; r < 4; r++) s[mi][nj][r] = 0.0f;

#pragma unroll
        for (int kc = 0; kc < 8; kc++) {
            unsigned a0[4], a1[4];
            int qb = (rw + g) * 68 + kc * 8 + t;
            a0[0] = Qs[qb];     a0[1] = Qs[qb + 8 * 68];
            a0[2] = Qs[qb + 4]; a0[3] = Qs[qb + 8 * 68 + 4];
            int qb1 = qb + 16 * 68;
            a1[0] = Qs[qb1];     a1[1] = Qs[qb1 + 8 * 68];
            a1[2] = Qs[qb1 + 4]; a1[3] = Qs[qb1 + 8 * 68 + 4];
#pragma unroll
            for (int nj = 0; nj < 8; nj++) {
                unsigned bf[2];
                int kb = (nj * 8 + g) * 68 + kc * 8 + t;
                bf[0] = Kc[kb]; bf[1] = Kc[kb + 4];
                mma8(s[0][nj], a0, bf);
                mma8(s[1][nj], a1, bf);
            }
        }

        // ---- mask + online softmax (4 row-groups) ----
#pragma unroll
        for (int mi = 0; mi < 2; mi++) {
            const float* mp0 = mask + (size_t)(q0 + rw + mi * 16 + g) * SEQ + k0;
            const float* mp1 = mp0 + (size_t)8 * SEQ;
            float mx0 = -1e30f, mx1 = -1e30f;
#pragma unroll
            for (int nj = 0; nj < 8; nj++) {
                float2 mk0 = *(const float2*)(mp0 + nj * 8 + 2 * t);
                float2 mk1 = *(const float2*)(mp1 + nj * 8 + 2 * t);
                s[mi][nj][0] += mk0.x; s[mi][nj][1] += mk0.y;
                s[mi][nj][2] += mk1.x; s[mi][nj][3] += mk1.y;
                mx0 = fmaxf(mx0, fmaxf(s[mi][nj][0], s[mi][nj][1]));
                mx1 = fmaxf(mx1, fmaxf(s[mi][nj][2], s[mi][nj][3]));
            }
            mx0 = fmaxf(mx0, __shfl_xor_sync(0xffffffffu, mx0, 1));
            mx0 = fmaxf(mx0, __shfl_xor_sync(0xffffffffu, mx0, 2));
            mx1 = fmaxf(mx1, __shfl_xor_sync(0xffffffffu, mx1, 1));
            mx1 = fmaxf(mx1, __shfl_xor_sync(0xffffffffu, mx1, 2));

            float mn0 = fmaxf(mrow[mi * 2], mx0), mn1 = fmaxf(mrow[mi * 2 + 1], mx1);
            float c0 = fast_exp(mrow[mi * 2] - mn0), c1 = fast_exp(mrow[mi * 2 + 1] - mn1);
            float sum0 = 0.0f, sum1 = 0.0f;
#pragma unroll
            for (int nj = 0; nj < 8; nj++) {
                s[mi][nj][0] = fast_exp(s[mi][nj][0] - mn0);
                s[mi][nj][1] = fast_exp(s[mi][nj][1] - mn0);
                s[mi][nj][2] = fast_exp(s[mi][nj][2] - mn1);
                s[mi][nj][3] = fast_exp(s[mi][nj][3] - mn1);
                sum0 += s[mi][nj][0] + s[mi][nj][1];
                sum1 += s[mi][nj][2] + s[mi][nj][3];
            }
            sum0 += __shfl_xor_sync(0xffffffffu, sum0, 1);
            sum0 += __shfl_xor_sync(0xffffffffu, sum0, 2);
            sum1 += __shfl_xor_sync(0xffffffffu, sum1, 1);
            sum1 += __shfl_xor_sync(0xffffffffu, sum1, 2);

            lrow[mi * 2]     = lrow[mi * 2] * c0 + sum0;
            lrow[mi * 2 + 1] = lrow[mi * 2 + 1] * c1 + sum1;
            mrow[mi * 2]     = mn0;
            mrow[mi * 2 + 1] = mn1;
#pragma unroll
            for (int nj = 0; nj < 8; nj++) {
                o[mi][nj][0] *= c0; o[mi][nj][1] *= c0;
                o[mi][nj][2] *= c1; o[mi][nj][3] *= c1;
            }
        }

        // ---- O += P @ V (P via shfl relayout) ----
#pragma unroll
        for (int kp = 0; kp < 4; kp++) {
            unsigned pe0[4], po0[4], pe1[4], po1[4];
            p_relayout(s[0][2 * kp],     pe0, lane, t);
            p_relayout(s[0][2 * kp + 1], po0, lane, t);
            p_relayout(s[1][2 * kp],     pe1, lane, t);
            p_relayout(s[1][2 * kp + 1], po1, lane, t);
#pragma unroll
            for (int oj = 0; oj < 8; oj++) {
                unsigned bA[2], bB[2];
                int vb = (kp * 16 + t) * 72 + oj * 8 + g;
                bA[0] = Vc[vb];           bA[1] = Vc[vb + 4 * 72];
                bB[0] = Vc[vb + 8 * 72];  bB[1] = Vc[vb + 12 * 72];
                mma8(o[0][oj], pe0, bA); mma8(o[0][oj], po0, bB);
                mma8(o[1][oj], pe1, bA); mma8(o[1][oj], po1, bB);
            }
        }
    }

    // ---- epilogue ----
#pragma unroll
    for (int mi = 0; mi < 2; mi++) {
        float inv0 = 1.0f / lrow[mi * 2], inv1 = 1.0f / lrow[mi * 2 + 1];
        const int r0g = q0 + rw + mi * 16 + g;
        float* o0 = out + base + (size_t)r0g * D_MODEL;
        float* o1 = o0 + (size_t)8 * D_MODEL;
#pragma unroll
        for (int nj = 0; nj < 8; nj++) {
            *(float2*)(o0 + nj * 8 + 2 * t) =
                make_float2(o[mi][nj][0] * inv0, o[mi][nj][1] * inv0);
            *(float2*)(o1 + nj * 8 + 2 * t) =
                make_float2(o[mi][nj][2] * inv1, o[mi][nj][3] * inv1);
        }
    }
}

// ---------------------------------------------------------------------------

extern "C" void kernel_launch(void* const* d_in, const int* in_sizes, int n_in,
                              void* d_out, int out_size)
{
    const float* q    = (const float*)d_in[0];
    const float* k    = (const float*)d_in[1];
    const float* v    = (const float*)d_in[2];
    const float* mask = (const float*)d_in[3];
    const float* Wq   = (const float*)d_in[4];
    const float* bq   = (const float*)d_in[5];
    const float* Wk   = (const float*)d_in[6];
    const float* bk   = (const float*)d_in[7];
    const float* Wv   = (const float*)d_in[8];
    const float* bv   = (const float*)d_in[9];
    float* out = (float*)d_out;

    float *qp, *kp, *vp, *xc, *wc;
    cudaGetSymbolAddress((void**)&qp, g_qp);
    cudaGetSymbolAddress((void**)&kp, g_kp);
    cudaGetSymbolAddress((void**)&vp, g_vp);
    cudaGetSymbolAddress((void**)&xc, g_xc);
    cudaGetSymbolAddress((void**)&wc, g_wc);
    float* xc0 = xc;
    float* xc1 = xc + (size_t)M_TOT * D_MODEL;
    float* xc2 = xc + (size_t)2 * M_TOT * D_MODEL;
    float* wc0 = wc;
    float* wc1 = wc + (size_t)D_MODEL * D_MODEL;
    float* wc2 = wc + (size_t)2 * D_MODEL * D_MODEL;

    const int nx4 = M_TOT * D_MODEL / 4;     // 1048576
    const int nw4 = D_MODEL * D_MODEL / 4;   // 262144
    conv_tf32<<<nx4 / 256, 256>>>((const float4*)q,  (float4*)xc0, nx4);
    conv_tf32<<<nx4 / 256, 256>>>((const float4*)k,  (float4*)xc1, nx4);
    conv_tf32<<<nx4 / 256, 256>>>((const float4*)v,  (float4*)xc2, nx4);
    conv_tf32<<<nw4 / 256, 256>>>((const float4*)Wq, (float4*)wc0, nw4);
    conv_tf32<<<nw4 / 256, 256>>>((const float4*)Wk, (float4*)wc1, nw4);
    conv_tf32<<<nw4 / 256, 256>>>((const float4*)Wv, (float4*)wc2, nw4);

    const int psmem = 4 * 4608 * (int)sizeof(unsigned);   // 73728 B
    cudaFuncSetAttribute(proj_tc3, cudaFuncAttributeMaxDynamicSharedMemorySize, psmem);
    proj_tc3<<<dim3(D_MODEL / 128, M_TOT / 128, 3), 256, psmem>>>(
        xc0, xc1, xc2, wc0, wc1, wc2, bq, bk, bv, qp, kp, vp);

    const int asmem = (8704 + 2 * 4352 + 2 * 4608) * (int)sizeof(unsigned);  // 106496 B
    cudaFuncSetAttribute(attn_tc3, cudaFuncAttributeMaxDynamicSharedMemorySize, asmem);
    attn_tc3<<<dim3(SEQ / 128, N_HEADS, BATCH), 128, asmem>>>(qp, kp, vp, mask, out);
}

// round 5
// speedup vs baseline: 1.9662x; 1.1716x over previous
#include <cuda_runtime.h>

#define D_MODEL 1024
#define N_HEADS 16
#define HEAD    64
#define BATCH   2
#define SEQ     2048
#define M_TOT   (BATCH * SEQ)

// Scratch (harness rules: __device__ globals only)
__device__ float g_qp[M_TOT * D_MODEL];
__device__ float g_kp[M_TOT * D_MODEL];
__device__ float g_vp[M_TOT * D_MODEL];
__device__ float g_xc[3][M_TOT * D_MODEL];     // tf32-converted q,k,v inputs
__device__ float g_wc[3][D_MODEL * D_MODEL];   // tf32-converted Wq,Wk,Wv

// ---------------------------------------------------------------------------
__device__ __forceinline__ unsigned f2tf(float x) {
    unsigned r;
    asm("cvt.rna.tf32.f32 %0, %1;" : "=r"(r) : "f"(x));
    return r;
}

__device__ __forceinline__ void mma8(float* d, const unsigned* a, const unsigned* b) {
    asm volatile(
        "mma.sync.aligned.m16n8k8.row.col.f32.tf32.tf32.f32 "
        "{%0,%1,%2,%3}, {%4,%5,%6,%7}, {%8,%9}, {%0,%1,%2,%3};\n"
        : "+f"(d[0]), "+f"(d[1]), "+f"(d[2]), "+f"(d[3])
        : "r"(a[0]), "r"(a[1]), "r"(a[2]), "r"(a[3]), "r"(b[0]), "r"(b[1]));
}

__device__ __forceinline__ void cp16(unsigned* smem_dst, const void* gsrc) {
    unsigned d = (unsigned)__cvta_generic_to_shared(smem_dst);
    asm volatile("cp.async.cg.shared.global [%0], [%1], 16;\n" :: "r"(d), "l"(gsrc));
}
#define CP_COMMIT asm volatile("cp.async.commit_group;\n" ::: "memory")
#define CP_WAIT0  asm volatile("cp.async.wait_group 0;\n" ::: "memory")

// e^x, FMA/ALU only (x<=0, clamped at -80)
__device__ __forceinline__ float fast_exp(float x) {
    x = fmaxf(x, -80.0f);
    float y  = x * 1.44269504088896f;
    float fy = y + 12582912.0f;
    int   k  = __float_as_int(fy);
    float f  = y - (fy - 12582912.0f);
    float p  = 1.33336e-3f;
    p = fmaf(p, f, 9.61812e-3f);
    p = fmaf(p, f, 5.55041e-2f);
    p = fmaf(p, f, 2.40226507e-1f);
    p = fmaf(p, f, 6.93147182e-1f);
    p = fmaf(p, f, 1.0f);
    return __int_as_float(__float_as_int(p) + (k << 23));
}

// ---------------------------------------------------------------------------
// Pre-convert fp32 -> tf32 bit pattern, all 6 tensors in one launch.
// blockIdx.y: 0..2 -> q,k,v (n4 = 1048576); 3..5 -> Wq,Wk,Wv (n4 = 262144)
// ---------------------------------------------------------------------------
__global__ __launch_bounds__(256) void conv_all(
    const float4* __restrict__ q, const float4* __restrict__ k, const float4* __restrict__ v,
    const float4* __restrict__ wq, const float4* __restrict__ wk, const float4* __restrict__ wv,
    float4* __restrict__ xc, float4* __restrict__ wc)
{
    const int y = blockIdx.y;
    const int nx4 = M_TOT * D_MODEL / 4;
    const int nw4 = D_MODEL * D_MODEL / 4;
    const float4* src;
    float4* dst;
    int n4;
    if (y < 3) {
        src = (y == 0) ? q : (y == 1) ? k : v;
        dst = xc + (size_t)y * nx4;
        n4 = nx4;
    } else {
        src = (y == 3) ? wq : (y == 4) ? wk : wv;
        dst = wc + (size_t)(y - 3) * nw4;
        n4 = nw4;
    }
    int i = blockIdx.x * 256 + threadIdx.x;
    if (i < n4) {
        float4 x = src[i];
        dst[i] = make_float4(__uint_as_float(f2tf(x.x)), __uint_as_float(f2tf(x.y)),
                             __uint_as_float(f2tf(x.z)), __uint_as_float(f2tf(x.w)));
    }
}

// ---------------------------------------------------------------------------
// Projection GEMM on pre-converted tf32 data. Y = X @ W^T + b, output as tf32
// bits (Q prescaled by 0.125). Block 128x128, BK=32 double-buffered cp.async,
// 8 warps (2m x 4n), warp tile 64x32. Row stride 36 words (conflict-free).
// ---------------------------------------------------------------------------
__global__ __launch_bounds__(256, 2) void proj_tc3(
    const float* __restrict__ x0, const float* __restrict__ x1, const float* __restrict__ x2,
    const float* __restrict__ w0, const float* __restrict__ w1, const float* __restrict__ w2,
    const float* __restrict__ bq, const float* __restrict__ bk, const float* __restrict__ bv,
    float* __restrict__ y0, float* __restrict__ y1, float* __restrict__ y2)
{
    const int z = blockIdx.z;
    const float* X    = (z == 0) ? x0 : (z == 1) ? x1 : x2;
    const float* W    = (z == 0) ? w0 : (z == 1) ? w1 : w2;
    const float* bias = (z == 0) ? bq : (z == 1) ? bk : bv;
    float*       Y    = (z == 0) ? y0 : (z == 1) ? y1 : y2;
    const float oscale = (z == 0) ? 0.125f : 1.0f;

    extern __shared__ unsigned psm[];
    unsigned* As = psm;             // [2][128*36]
    unsigned* Bs = psm + 2 * 4608;  // [2][128*36]

    const int tid = threadIdx.x, lane = tid & 31, wid = tid >> 5;
    const int wm = wid >> 2, wn = wid & 3;
    const int g = lane >> 2, t = lane & 3;
    const int bm = blockIdx.y * 128, bn = blockIdx.x * 128;

    const int frow = tid >> 3;        // 0..31, +p*32
    const int fc4  = (tid & 7) * 4;   // 0..28

    float acc[4][4][4];
#pragma unroll
    for (int mi = 0; mi < 4; mi++)
#pragma unroll
        for (int nj = 0; nj < 4; nj++)
#pragma unroll
            for (int r = 0; r < 4; r++) acc[mi][nj][r] = 0.0f;

    // prologue fill buf 0
    {
        const float* Xs = X + (size_t)bm * D_MODEL + fc4;
        const float* Ws = W + (size_t)bn * D_MODEL + fc4;
#pragma unroll
        for (int p = 0; p < 4; p++) {
            int row = frow + p * 32;
            cp16(As + row * 36 + fc4, Xs + (size_t)row * D_MODEL);
            cp16(Bs + row * 36 + fc4, Ws + (size_t)row * D_MODEL);
        }
        CP_COMMIT;
    }

    for (int it = 0; it < 32; it++) {
        CP_WAIT0;
        __syncthreads();
        if (it < 31) {
            int buf = (it + 1) & 1;
            int k0 = (it + 1) * 32;
            const float* Xs = X + (size_t)bm * D_MODEL + k0 + fc4;
            const float* Ws = W + (size_t)bn * D_MODEL + k0 + fc4;
            unsigned* Ab = As + buf * 4608;
            unsigned* Bb = Bs + buf * 4608;
#pragma unroll
            for (int p = 0; p < 4; p++) {
                int row = frow + p * 32;
                cp16(Ab + row * 36 + fc4, Xs + (size_t)row * D_MODEL);
                cp16(Bb + row * 36 + fc4, Ws + (size_t)row * D_MODEL);
            }
            CP_COMMIT;
        }
        const unsigned* Ab = As + (it & 1) * 4608;
        const unsigned* Bb = Bs + (it & 1) * 4608;
#pragma unroll
        for (int kk = 0; kk < 4; kk++) {
            unsigned af[4][4], bf[4][2];
#pragma unroll
            for (int mi = 0; mi < 4; mi++) {
                int ba = (wm * 64 + mi * 16 + g) * 36 + kk * 8 + t;
                af[mi][0] = Ab[ba];     af[mi][1] = Ab[ba + 8 * 36];
                af[mi][2] = Ab[ba + 4]; af[mi][3] = Ab[ba + 8 * 36 + 4];
            }
#pragma unroll
            for (int nj = 0; nj < 4; nj++) {
                int bb = (wn * 32 + nj * 8 + g) * 36 + kk * 8 + t;
                bf[nj][0] = Bb[bb]; bf[nj][1] = Bb[bb + 4];
            }
#pragma unroll
            for (int mi = 0; mi < 4; mi++)
#pragma unroll
                for (int nj = 0; nj < 4; nj++)
                    mma8(acc[mi][nj], af[mi], bf[nj]);
        }
    }

#pragma unroll
    for (int mi = 0; mi < 4; mi++) {
        int r0 = bm + wm * 64 + mi * 16 + g;
#pragma unroll
        for (int nj = 0; nj < 4; nj++) {
            int c = bn + wn * 32 + nj * 8 + 2 * t;
            float bb0 = bias[c], bb1 = bias[c + 1];
            float v0 = (acc[mi][nj][0] + bb0) * oscale;
            float v1 = (acc[mi][nj][1] + bb1) * oscale;
            float v2 = (acc[mi][nj][2] + bb0) * oscale;
            float v3 = (acc[mi][nj][3] + bb1) * oscale;
            *(float2*)(Y + (size_t)r0 * D_MODEL + c) =
                make_float2(__uint_as_float(f2tf(v0)), __uint_as_float(f2tf(v1)));
            *(float2*)(Y + (size_t)(r0 + 8) * D_MODEL + c) =
                make_float2(__uint_as_float(f2tf(v2)), __uint_as_float(f2tf(v3)));
        }
    }
}

// ---------------------------------------------------------------------------
// Flash attention. Inputs already tf32 bits (Q prescaled). 256 thr / 8 warps,
// q-tile 128 (16 rows/warp = 1 m16), key tiles of 64, double-buffered cp.async.
// Strides: Q/K 68 (bank = 4g+t), V 72 (bank = 8t+g) -> all conflict-free.
// Target 2 CTAs/SM (regs <= 128, smem 2x106.5KB).
// ---------------------------------------------------------------------------
__device__ __forceinline__ void p_relayout(const float* s, unsigned* a, int lane, int t) {
    const int srcA = (lane & 28) | (t >> 1);
    const int srcB = srcA + 2;
    float u0 = __shfl_sync(0xffffffffu, s[0], srcA);
    float u1 = __shfl_sync(0xffffffffu, s[1], srcA);
    float v0 = __shfl_sync(0xffffffffu, s[2], srcA);
    float v1 = __shfl_sync(0xffffffffu, s[3], srcA);
    float w0 = __shfl_sync(0xffffffffu, s[0], srcB);
    float w1 = __shfl_sync(0xffffffffu, s[1], srcB);
    float x0 = __shfl_sync(0xffffffffu, s[2], srcB);
    float x1 = __shfl_sync(0xffffffffu, s[3], srcB);
    bool odd = (t & 1);
    a[0] = f2tf(odd ? u1 : u0);
    a[1] = f2tf(odd ? v1 : v0);
    a[2] = f2tf(odd ? w1 : w0);
    a[3] = f2tf(odd ? x1 : x0);
}

__global__ __launch_bounds__(256, 2) void attn_tc4(
    const float* __restrict__ QP, const float* __restrict__ KP,
    const float* __restrict__ VP, const float* __restrict__ mask,
    float* __restrict__ out)
{
    extern __shared__ unsigned smbuf[];
    unsigned* Qs = smbuf;             // 128*68 = 8704 words
    unsigned* Ks = smbuf + 8704;      // 2 x 64*68 (4352 each)
    unsigned* Vs = smbuf + 17408;     // 2 x 64*72 (4608 each)

    const int tid = threadIdx.x, lane = tid & 31, wid = tid >> 5;
    const int g = lane >> 2, t = lane & 3;
    const int rw = wid * 16;
    const int q0 = blockIdx.x * 128;
    const int h = blockIdx.y, b = blockIdx.z;
    const size_t base = (size_t)b * SEQ * D_MODEL + (size_t)h * HEAD;

    const int frow = tid >> 4;        // 0..15
    const int fc4  = (tid & 15) * 4;  // 0..60

    // Q fill (once) + KV tile 0, one cp.async group
    {
        const float* Qsrc = QP + base + (size_t)q0 * D_MODEL + fc4;
#pragma unroll
        for (int p = 0; p < 8; p++) {
            int row = frow + p * 16;
            cp16(Qs + row * 68 + fc4, Qsrc + (size_t)row * D_MODEL);
        }
        const float* Ksrc = KP + base + fc4;
        const float* Vsrc = VP + base + fc4;
#pragma unroll
        for (int p = 0; p < 4; p++) {
            int row = frow + p * 16;
            cp16(Ks + row * 68 + fc4, Ksrc + (size_t)row * D_MODEL);
            cp16(Vs + row * 72 + fc4, Vsrc + (size_t)row * D_MODEL);
        }
        CP_COMMIT;
    }

    float o[8][4];
#pragma unroll
    for (int nj = 0; nj < 8; nj++)
#pragma unroll
        for (int r = 0; r < 4; r++) o[nj][r] = 0.0f;
    float m0 = -1e30f, m1 = -1e30f, l0 = 0.0f, l1 = 0.0f;

    const float* mp0 = mask + (size_t)(q0 + rw + g) * SEQ;
    const float* mp1 = mp0 + (size_t)8 * SEQ;

    for (int it = 0; it < SEQ / 64; it++) {
        CP_WAIT0;
        __syncthreads();
        if (it + 1 < SEQ / 64) {
            int buf = (it + 1) & 1;
            const float* Ksrc = KP + base + (size_t)(it + 1) * 64 * D_MODEL + fc4;
            const float* Vsrc = VP + base + (size_t)(it + 1) * 64 * D_MODEL + fc4;
            unsigned* Kb = Ks + buf * 4352;
            unsigned* Vb = Vs + buf * 4608;
#pragma unroll
            for (int p = 0; p < 4; p++) {
                int row = frow + p * 16;
                cp16(Kb + row * 68 + fc4, Ksrc + (size_t)row * D_MODEL);
                cp16(Vb + row * 72 + fc4, Vsrc + (size_t)row * D_MODEL);
            }
            CP_COMMIT;
        }
        const unsigned* Kc = Ks + (it & 1) * 4352;
        const unsigned* Vc = Vs + (it & 1) * 4608;
        const int k0 = it * 64;

        // ---- S = Q @ K^T (warp: 16 q-rows x 64 keys) ----
        float s[8][4];
#pragma unroll
        for (int nj = 0; nj < 8; nj++)
#pragma unroll
            for (int r = 0; r < 4; r++) s[nj][r] = 0.0f;

#pragma unroll
        for (int kc = 0; kc < 8; kc++) {
            unsigned a[4];
            int qb = (rw + g) * 68 + kc * 8 + t;
            a[0] = Qs[qb];     a[1] = Qs[qb + 8 * 68];
            a[2] = Qs[qb + 4]; a[3] = Qs[qb + 8 * 68 + 4];
#pragma unroll
            for (int nj = 0; nj < 8; nj++) {
                unsigned bf[2];
                int kb = (nj * 8 + g) * 68 + kc * 8 + t;
                bf[0] = Kc[kb]; bf[1] = Kc[kb + 4];
                mma8(s[nj], a, bf);
            }
        }

        // ---- mask + online softmax ----
        float mx0 = -1e30f, mx1 = -1e30f;
#pragma unroll
        for (int nj = 0; nj < 8; nj++) {
            float2 mk0 = *(const float2*)(mp0 + k0 + nj * 8 + 2 * t);
            float2 mk1 = *(const float2*)(mp1 + k0 + nj * 8 + 2 * t);
            s[nj][0] += mk0.x; s[nj][1] += mk0.y;
            s[nj][2] += mk1.x; s[nj][3] += mk1.y;
            mx0 = fmaxf(mx0, fmaxf(s[nj][0], s[nj][1]));
            mx1 = fmaxf(mx1, fmaxf(s[nj][2], s[nj][3]));
        }
        mx0 = fmaxf(mx0, __shfl_xor_sync(0xffffffffu, mx0, 1));
        mx0 = fmaxf(mx0, __shfl_xor_sync(0xffffffffu, mx0, 2));
        mx1 = fmaxf(mx1, __shfl_xor_sync(0xffffffffu, mx1, 1));
        mx1 = fmaxf(mx1, __shfl_xor_sync(0xffffffffu, mx1, 2));

        float mn0 = fmaxf(m0, mx0), mn1 = fmaxf(m1, mx1);
        float c0 = fast_exp(m0 - mn0), c1 = fast_exp(m1 - mn1);
        float sum0 = 0.0f, sum1 = 0.0f;
#pragma unroll
        for (int nj = 0; nj < 8; nj++) {
            s[nj][0] = fast_exp(s[nj][0] - mn0);
            s[nj][1] = fast_exp(s[nj][1] - mn0);
            s[nj][2] = fast_exp(s[nj][2] - mn1);
            s[nj][3] = fast_exp(s[nj][3] - mn1);
            sum0 += s[nj][0] + s[nj][1];
            sum1 += s[nj][2] + s[nj][3];
        }
        sum0 += __shfl_xor_sync(0xffffffffu, sum0, 1);
        sum0 += __shfl_xor_sync(0xffffffffu, sum0, 2);
        sum1 += __shfl_xor_sync(0xffffffffu, sum1, 1);
        sum1 += __shfl_xor_sync(0xffffffffu, sum1, 2);

        l0 = l0 * c0 + sum0;  l1 = l1 * c1 + sum1;
        m0 = mn0;             m1 = mn1;
#pragma unroll
        for (int nj = 0; nj < 8; nj++) {
            o[nj][0] *= c0; o[nj][1] *= c0;
            o[nj][2] *= c1; o[nj][3] *= c1;
        }

        // ---- O += P @ V (P via shfl relayout) ----
#pragma unroll
        for (int kp = 0; kp < 4; kp++) {
            unsigned pe[4], po[4];
            p_relayout(s[2 * kp],     pe, lane, t);
            p_relayout(s[2 * kp + 1], po, lane, t);
#pragma unroll
            for (int oj = 0; oj < 8; oj++) {
                unsigned bA[2], bB[2];
                int vb = (kp * 16 + t) * 72 + oj * 8 + g;
                bA[0] = Vc[vb];           bA[1] = Vc[vb + 4 * 72];
                bB[0] = Vc[vb + 8 * 72];  bB[1] = Vc[vb + 12 * 72];
                mma8(o[oj], pe, bA);
                mma8(o[oj], po, bB);
            }
        }
    }

    // ---- epilogue ----
    float inv0 = 1.0f / l0, inv1 = 1.0f / l1;
    const int r0g = q0 + rw + g;
    float* o0 = out + base + (size_t)r0g * D_MODEL;
    float* o1 = o0 + (size_t)8 * D_MODEL;
#pragma unroll
    for (int nj = 0; nj < 8; nj++) {
        *(float2*)(o0 + nj * 8 + 2 * t) = make_float2(o[nj][0] * inv0, o[nj][1] * inv0);
        *(float2*)(o1 + nj * 8 + 2 * t) = make_float2(o[nj][2] * inv1, o[nj][3] * inv1);
    }
}

// ---------------------------------------------------------------------------

extern "C" void kernel_launch(void* const* d_in, const int* in_sizes, int n_in,
                              void* d_out, int out_size)
{
    const float* q    = (const float*)d_in[0];
    const float* k    = (const float*)d_in[1];
    const float* v    = (const float*)d_in[2];
    const float* mask = (const float*)d_in[3];
    const float* Wq   = (const float*)d_in[4];
    const float* bq   = (const float*)d_in[5];
    const float* Wk   = (const float*)d_in[6];
    const float* bk   = (const float*)d_in[7];
    const float* Wv   = (const float*)d_in[8];
    const float* bv   = (const float*)d_in[9];
    float* out = (float*)d_out;

    float *qp, *kp, *vp, *xc, *wc;
    cudaGetSymbolAddress((void**)&qp, g_qp);
    cudaGetSymbolAddress((void**)&kp, g_kp);
    cudaGetSymbolAddress((void**)&vp, g_vp);
    cudaGetSymbolAddress((void**)&xc, g_xc);
    cudaGetSymbolAddress((void**)&wc, g_wc);
    float* xc0 = xc;
    float* xc1 = xc + (size_t)M_TOT * D_MODEL;
    float* xc2 = xc + (size_t)2 * M_TOT * D_MODEL;
    float* wc0 = wc;
    float* wc1 = wc + (size_t)D_MODEL * D_MODEL;
    float* wc2 = wc + (size_t)2 * D_MODEL * D_MODEL;

    const int nx4 = M_TOT * D_MODEL / 4;     // 1048576
    conv_all<<<dim3(nx4 / 256, 6), 256>>>(
        (const float4*)q, (const float4*)k, (const float4*)v,
        (const float4*)Wq, (const float4*)Wk, (const float4*)Wv,
        (float4*)xc, (float4*)wc);

    const int psmem = 4 * 4608 * (int)sizeof(unsigned);   // 73728 B
    cudaFuncSetAttribute(proj_tc3, cudaFuncAttributeMaxDynamicSharedMemorySize, psmem);
    proj_tc3<<<dim3(D_MODEL / 128, M_TOT / 128, 3), 256, psmem>>>(
        xc0, xc1, xc2, wc0, wc1, wc2, bq, bk, bv, qp, kp, vp);

    const int asmem = (8704 + 2 * 4352 + 2 * 4608) * (int)sizeof(unsigned);  // 106496 B
    cudaFuncSetAttribute(attn_tc4, cudaFuncAttributeMaxDynamicSharedMemorySize, asmem);
    attn_tc4<<<dim3(SEQ / 128, N_HEADS, BATCH), 256, asmem>>>(qp, kp, vp, mask, out);
}